// round 16
// baseline (speedup 1.0000x reference)
#include <cuda_runtime.h>

// SSConv2d: per-pixel input-group routed 3x3 conv (64 oc) + maxout group select.
// fp32 FFMA2 path. Block = 32x8 output tile, 256 threads, 2 CTAs/SM (16 warps,
// RF-capped). 16 half-warp slots allocated to groups proportionally to work.
// Each slot holds its (tap,g) weight slice (16c x 4oc) in registers; the NEXT
// tap's slice is LDG'd into the same (dead) registers BEFORE the per-tap
// barrier. Interior entries are uint2 with precomputed byte offsets; edge
// pixels expand into dense per-(g,tap) buckets. BOTH hot loops are 2-wide
// (two independent fma chains in flight before commits). acc in padded smem
// tile with per-tap exclusive ownership (barrier between taps => race free).

#define TX 32
#define TY 8
#define NPIX (TX * TY)      // 256
#define IN_W 34
#define IN_H 10
#define NIN (IN_W * IN_H)   // 340
#define ACC_STRIDE 68       // 68 floats = 272 B per pixel row
#define NTHREADS 256
#define FULL_CAP 184        // interior pixels: max 6*30 = 180
#define EPOOL_CAP 968       // edge expansion: max 160 px * 6 valid taps = 960

typedef unsigned long long ull;

// pre-packed weights: [tap(9)][g(4)][c2(8)][q(2)][ocg(16)][4 floats]
__device__ float g_wp[9 * 4 * 8 * 2 * 16 * 4];

__global__ void prepack_w(const float* __restrict__ w) {
    int i = blockIdx.x * blockDim.x + threadIdx.x;
    if (i >= 36864) return;
    int j   = i & 3;
    int ocg = (i >> 2) & 15;
    int q   = (i >> 6) & 1;
    int c2  = (i >> 7) & 7;
    int g   = (i >> 10) & 3;
    int tap = i >> 12;
    int oc = ocg * 4 + q * 2 + (j >> 1);
    int c  = c2 * 2 + (j & 1);
    g_wp[i] = w[(oc * 64 + g * 16 + c) * 9 + tap];
}

__device__ __forceinline__ void unpack2(float& lo, float& hi, ull v) {
    asm("mov.b64 {%0, %1}, %2;" : "=f"(lo), "=f"(hi) : "l"(v));
}
__device__ __forceinline__ ull pack2(float lo, float hi) {
    ull r;
    asm("mov.b64 %0, {%1, %2};" : "=l"(r) : "f"(lo), "f"(hi));
    return r;
}
__device__ __forceinline__ ull fma2(ull a, ull b, ull c) {
    ull d;
    asm("fma.rn.f32x2 %0, %1, %2, %3;" : "=l"(d) : "l"(a), "l"(b), "l"(c));
    return d;
}
__device__ __forceinline__ ull mul2(ull a, ull b) {
    ull d;
    asm("mul.rn.f32x2 %0, %1, %2;" : "=l"(d) : "l"(a), "l"(b));
    return d;
}
__device__ __forceinline__ ull add2(ull a, ull b) {
    ull d;
    asm("add.rn.f32x2 %0, %1, %2;" : "=l"(d) : "l"(a), "l"(b));
    return d;
}

struct PixAcc {
    ull a0, a1, a2, a3;
    float* ap;
};

// partial dot (16c x 4oc) for one pixel, byte-offset addressed
__device__ __forceinline__ PixAcc pix_compute(
    int xoffB, int accoffB, const char* xb, char* accb,
    const ull (&wA)[8], const ull (&wB)[8], const ull (&wC)[8], const ull (&wD)[8])
{
    PixAcc r;
    r.ap = (float*)(accb + accoffB);
    const ulonglong2* xp = (const ulonglong2*)(xb + xoffB);
    ulonglong2 p0 = xp[0];
    ulonglong2 p1 = xp[1];
    r.a0 = mul2(wA[0], p0.x);
    r.a1 = mul2(wB[0], p0.x);
    r.a2 = mul2(wC[0], p0.x);
    r.a3 = mul2(wD[0], p0.x);
    r.a0 = fma2(wA[1], p0.y, r.a0);
    r.a1 = fma2(wB[1], p0.y, r.a1);
    r.a2 = fma2(wC[1], p0.y, r.a2);
    r.a3 = fma2(wD[1], p0.y, r.a3);
    r.a0 = fma2(wA[2], p1.x, r.a0);
    r.a1 = fma2(wB[2], p1.x, r.a1);
    r.a2 = fma2(wC[2], p1.x, r.a2);
    r.a3 = fma2(wD[2], p1.x, r.a3);
    r.a0 = fma2(wA[3], p1.y, r.a0);
    r.a1 = fma2(wB[3], p1.y, r.a1);
    r.a2 = fma2(wC[3], p1.y, r.a2);
    r.a3 = fma2(wD[3], p1.y, r.a3);
    ulonglong2 p2 = xp[2];
    ulonglong2 p3 = xp[3];
    r.a0 = fma2(wA[4], p2.x, r.a0);
    r.a1 = fma2(wB[4], p2.x, r.a1);
    r.a2 = fma2(wC[4], p2.x, r.a2);
    r.a3 = fma2(wD[4], p2.x, r.a3);
    r.a0 = fma2(wA[5], p2.y, r.a0);
    r.a1 = fma2(wB[5], p2.y, r.a1);
    r.a2 = fma2(wC[5], p2.y, r.a2);
    r.a3 = fma2(wD[5], p2.y, r.a3);
    r.a0 = fma2(wA[6], p3.x, r.a0);
    r.a1 = fma2(wB[6], p3.x, r.a1);
    r.a2 = fma2(wC[6], p3.x, r.a2);
    r.a3 = fma2(wD[6], p3.x, r.a3);
    r.a0 = fma2(wA[7], p3.y, r.a0);
    r.a1 = fma2(wB[7], p3.y, r.a1);
    r.a2 = fma2(wC[7], p3.y, r.a2);
    r.a3 = fma2(wD[7], p3.y, r.a3);
    return r;
}

// commit (R12/R14 style): same-chain unpack/pack are register no-ops;
// 4 FADD + 2 packed adds into the acc row
__device__ __forceinline__ void pix_commit(const PixAcc& r) {
    ulonglong2* ap2 = (ulonglong2*)r.ap;
    ulonglong2 av = *ap2;
    float l, h, s0, s1, s2, s3;
    unpack2(l, h, r.a0); s0 = l + h;
    unpack2(l, h, r.a1); s1 = l + h;
    unpack2(l, h, r.a2); s2 = l + h;
    unpack2(l, h, r.a3); s3 = l + h;
    av.x = add2(av.x, pack2(s0, s1));
    av.y = add2(av.y, pack2(s2, s3));
    *ap2 = av;
}

#define SMEM_BYTES ((NIN * 16 + NPIX * ACC_STRIDE) * 4 + \
                    4 * FULL_CAP * 8 + EPOOL_CAP * 8 + 448)

extern __shared__ float smem_dyn[];

__global__ __launch_bounds__(NTHREADS, 2)
void ssconv_main(const float* __restrict__ x, const int* __restrict__ gidx,
                 const float* __restrict__ bias, float* __restrict__ out,
                 float* __restrict__ out_idx, int write_idx) {
    float* x_s = smem_dyn;
    float* acc_s = x_s + NIN * 16;
    uint2* fl = (uint2*)(acc_s + NPIX * ACC_STRIDE);
    uint2* epool = fl + 4 * FULL_CAP;
    int* cntf = (int*)(epool + EPOOL_CAP);   // [4]
    int* cnte = cntf + 4;                    // [36] per-(g,tap) counts
    int* start_s = cnte + 36;                // [36] bucket starts
    int* cursor_s = start_s + 36;            // [36] fill cursors

    const int t = threadIdx.x;
    const int b = blockIdx.z;
    const int oy0 = blockIdx.y * TY;
    const int ox0 = blockIdx.x * TX;

    if (t < 40) cntf[t] = 0;   // cntf[0..3] + cnte[0..35]
    __syncthreads();

    // ---- load input tile (with halo) into smem ----
    for (int f = t; f < NIN * 4; f += NTHREADS) {
        int p = f >> 2, c4 = f & 3;
        int ly = p / IN_W, lx = p - ly * IN_W;
        int iy = oy0 - 1 + ly, ix = ox0 - 1 + lx;
        float4 v = make_float4(0.f, 0.f, 0.f, 0.f);
        if ((unsigned)iy < 256u && (unsigned)ix < 256u)
            v = *(const float4*)(x + (((size_t)b * 256 + iy) * 256 + ix) * 16 + c4 * 4);
        *(float4*)(x_s + p * 16 + c4 * 4) = v;
    }
    // ---- pass A: classify; interior push, edge per-(g,tap) counting ----
    for (int p = t; p < NIN; p += NTHREADS) {
        int ly = p / IN_W, lx = p - ly * IN_W;
        int iy = oy0 - 1 + ly, ix = ox0 - 1 + lx;
        if ((unsigned)iy < 256u && (unsigned)ix < 256u) {
            int g = gidx[((size_t)b * 256 + iy) * 256 + ix];
            unsigned xoffB = (unsigned)p * 64u;
            unsigned posB = (unsigned)(ly * TX + lx) * (ACC_STRIDE * 4);
            bool full = (ly >= 2) & (ly <= TY - 1) & (lx >= 2) & (lx <= TX - 1);
            if (full) {
                fl[g * FULL_CAP + atomicAdd(&cntf[g], 1)] =
                    make_uint2(xoffB, posB);
            } else {
                unsigned C = (lx <= TX - 1 ? 1u : 0u) |
                             ((lx >= 1 && lx <= TX ? 1u : 0u) << 1) |
                             ((lx >= 2 ? 1u : 0u) << 2);
                unsigned mask =
                    (ly <= TY - 1 ? C : 0u) |
                    ((ly >= 1 && ly <= TY ? C : 0u) << 3) |
                    ((ly >= 2 ? C : 0u) << 6);
                for (int tp = 0; tp < 9; tp++)
                    if ((mask >> tp) & 1u) atomicAdd(&cnte[g * 9 + tp], 1);
            }
        }
    }
    // ---- init accumulators to bias (overlaps with counting) ----
    for (int f = t; f < NPIX * 17; f += NTHREADS) {
        int c4 = f % 17;
        float4 v = make_float4(0.f, 0.f, 0.f, 0.f);
        if (c4 < 16) v = *(const float4*)(bias + c4 * 4);
        ((float4*)acc_s)[f] = v;
    }
    __syncthreads();

    // ---- scan: bucket starts + cursors (single thread, 36 elems) ----
    if (t == 0) {
        int acc = 0;
        for (int i = 0; i < 36; i++) {
            start_s[i] = acc;
            cursor_s[i] = acc;
            acc += cnte[i];
        }
    }
    __syncthreads();

    // ---- pass C: fill dense edge buckets with ABSOLUTE acc offsets ----
    for (int p = t; p < NIN; p += NTHREADS) {
        int ly = p / IN_W, lx = p - ly * IN_W;
        int iy = oy0 - 1 + ly, ix = ox0 - 1 + lx;
        if ((unsigned)iy < 256u && (unsigned)ix < 256u) {
            bool full = (ly >= 2) & (ly <= TY - 1) & (lx >= 2) & (lx <= TX - 1);
            if (!full) {
                int g = gidx[((size_t)b * 256 + iy) * 256 + ix];
                unsigned xoffB = (unsigned)p * 64u;
                unsigned posB = (unsigned)(ly * TX + lx) * (ACC_STRIDE * 4);
                unsigned C = (lx <= TX - 1 ? 1u : 0u) |
                             ((lx >= 1 && lx <= TX ? 1u : 0u) << 1) |
                             ((lx >= 2 ? 1u : 0u) << 2);
                unsigned mask =
                    (ly <= TY - 1 ? C : 0u) |
                    ((ly >= 1 && ly <= TY ? C : 0u) << 3) |
                    ((ly >= 2 ? C : 0u) << 6);
                for (int tp = 0; tp < 9; tp++) {
                    if ((mask >> tp) & 1u) {
                        unsigned tapoffB =
                            (unsigned)(((tp / 3) * TX + (tp % 3)) * (ACC_STRIDE * 4));
                        int idx = atomicAdd(&cursor_s[g * 9 + tp], 1);
                        epool[idx] = make_uint2(xoffB, posB - tapoffB);
                    }
                }
            }
        }
    }
    __syncthreads();

    // ---- proportional slot allocation: 16 half-warp slots over 4 groups ----
    const int nf0 = cntf[0], nf1 = cntf[1], nf2 = cntf[2], nf3 = cntf[3];
    int ge0 = 0, ge1 = 0, ge2 = 0, ge3 = 0;
    for (int i = 0; i < 9; i++) {
        ge0 += cnte[i];
        ge1 += cnte[9 + i];
        ge2 += cnte[18 + i];
        ge3 += cnte[27 + i];
    }
    const int w0 = 4 * nf0 + ge0, w1 = 4 * nf1 + ge1;
    const int w2 = 4 * nf2 + ge2, w3 = 4 * nf3 + ge3;
    const int W = w0 + w1 + w2 + w3;   // never 0
    int e0 = 12 * w0 / W, e1 = 12 * w1 / W, e2 = 12 * w2 / W, e3 = 12 * w3 / W;
    int rem = 12 - (e0 + e1 + e2 + e3);
    int f0 = 12 * w0 - e0 * W, f1 = 12 * w1 - e1 * W;
    int f2 = 12 * w2 - e2 * W, f3 = 12 * w3 - e3 * W;
    int r0 = (f1 > f0) + (f2 > f0) + (f3 > f0);
    int r1 = (f0 >= f1) + (f2 > f1) + (f3 > f1);
    int r2 = (f0 >= f2) + (f1 >= f2) + (f3 > f2);
    int r3 = (f0 >= f3) + (f1 >= f3) + (f2 >= f3);
    int s0 = 1 + e0 + (r0 < rem), s1 = 1 + e1 + (r1 < rem);
    int s2 = 1 + e2 + (r2 < rem), s3 = 1 + e3 + (r3 < rem);
    const int S1 = s0, S2 = s0 + s1, S3 = s0 + s1 + s2;

    const int k = t >> 4;  // slot id 0..15
    const int g = (k >= S1) + (k >= S2) + (k >= S3);
    const int rank = k - (g == 0 ? 0 : g == 1 ? S1 : g == 2 ? S2 : S3);
    const int sg = (g == 0 ? s0 : g == 1 ? s1 : g == 2 ? s2 : s3);
    const int nf = (g == 0 ? nf0 : g == 1 ? nf1 : g == 2 ? nf2 : nf3);
    const uint2* Lf = fl + g * FULL_CAP;

    const int ocg = t & 15;
    const char* xb = (const char*)x_s;
    char* accb = (char*)acc_s + ocg * 16;

    // ---- preload tap 0 weights ----
    ull wA[8], wB[8], wC[8], wD[8];
    {
        const ulonglong2* wq = (const ulonglong2*)(g_wp + g * 1024) + ocg;
#pragma unroll
        for (int c2 = 0; c2 < 8; c2++) {
            ulonglong2 q0 = wq[c2 * 32];
            ulonglong2 q1 = wq[c2 * 32 + 16];
            wA[c2] = q0.x; wB[c2] = q0.y;
            wC[c2] = q1.x; wD[c2] = q1.y;
        }
    }

#pragma unroll 1
    for (int tap = 0; tap < 9; tap++) {
        const int ky = tap / 3;
        const int kx = tap - ky * 3;
        const int tapoffB = (ky * TX + kx) * (ACC_STRIDE * 4);

        // full-interior list: checkless, 2 pixels via one LDS.128 entry pair
        {
            int i = rank * 2;                // 16B-aligned pair start
            const int step = sg * 2;
            for (; i + 1 < nf; i += step) {
                uint4 uu = *(const uint4*)(Lf + i);
                PixAcc A = pix_compute((int)uu.x, (int)uu.y - tapoffB,
                                       xb, accb, wA, wB, wC, wD);
                PixAcc B = pix_compute((int)uu.z, (int)uu.w - tapoffB,
                                       xb, accb, wA, wB, wC, wD);
                pix_commit(A);
                pix_commit(B);
            }
            if (i < nf) {
                uint2 u0 = Lf[i];
                PixAcc A = pix_compute((int)u0.x, (int)u0.y - tapoffB,
                                       xb, accb, wA, wB, wC, wD);
                pix_commit(A);
            }
        }
        // dense edge bucket for (g, tap): branchless, 2-wide for ILP
        {
            const int gt = g * 9 + tap;
            const int base = start_s[gt];
            const int n = cnte[gt];
            int i = rank * 2;
            const int step = sg * 2;
            for (; i + 1 < n; i += step) {
                uint2 eA = epool[base + i];
                uint2 eB = epool[base + i + 1];
                PixAcc A = pix_compute((int)eA.x, (int)eA.y,
                                       xb, accb, wA, wB, wC, wD);
                PixAcc B = pix_compute((int)eB.x, (int)eB.y,
                                       xb, accb, wA, wB, wC, wD);
                pix_commit(A);
                pix_commit(B);
            }
            if (i < n) {
                uint2 e = epool[base + i];
                PixAcc A = pix_compute((int)e.x, (int)e.y,
                                       xb, accb, wA, wB, wC, wD);
                pix_commit(A);
            }
        }

        // ---- prefetch NEXT tap's weights (float-unit pointer arithmetic!)
        //      into the now-dead registers BEFORE the barrier
        if (tap < 8) {
            const ulonglong2* wq =
                (const ulonglong2*)(g_wp + ((tap + 1) * 4 + g) * 1024) + ocg;
#pragma unroll
            for (int c2 = 0; c2 < 8; c2++) {
                ulonglong2 q0 = wq[c2 * 32];
                ulonglong2 q1 = wq[c2 * 32 + 16];
                wA[c2] = q0.x; wB[c2] = q0.y;
                wC[c2] = q1.x; wD[c2] = q1.y;
            }
        }
        __syncthreads();  // acc ownership handoff between taps
    }

    // ---- epilogue: maxout group selection, one thread per pixel ----
    {
        const float* ar = acc_s + t * ACC_STRIDE;
        float best = -3.4e38f;
        int bi = 0;
#pragma unroll
        for (int og = 0; og < 4; og++) {
            float m = -3.4e38f;
#pragma unroll
            for (int kk = 0; kk < 16; kk += 4) {
                float4 v = *(const float4*)(ar + og * 16 + kk);
                m = fmaxf(m, fmaxf(fmaxf(v.x, v.y), fmaxf(v.z, v.w)));
            }
            if (m > best) { best = m; bi = og; }  // first-max tie-break
        }
        int pyl = t >> 5, pxl = t & 31;
        size_t opix = ((size_t)b * 256 + (oy0 + pyl)) * 256 + (ox0 + pxl);
        float4* op = (float4*)(out + opix * 16);
        const float4* sp = (const float4*)(ar + bi * 16);
        op[0] = sp[0];
        op[1] = sp[1];
        op[2] = sp[2];
        op[3] = sp[3];
        if (write_idx) out_idx[opix] = (float)bi;
    }
}

extern "C" void kernel_launch(void* const* d_in, const int* in_sizes, int n_in,
                              void* d_out, int out_size) {
    const float* x = (const float*)d_in[0];
    const int* gi = (const int*)d_in[1];
    const float* w = (const float*)d_in[2];
    const float* bias = (const float*)d_in[3];
    float* out = (float*)d_out;

    const int n_sel = in_sizes[0];  // B*H*W*16 (sel output size)
    const int n_pix = in_sizes[1];  // B*H*W
    const int B = n_pix / (256 * 256);
    const int write_idx = (out_size >= n_sel + n_pix) ? 1 : 0;

    prepack_w<<<(36864 + 255) / 256, 256>>>(w);

    cudaFuncSetAttribute(ssconv_main, cudaFuncAttributeMaxDynamicSharedMemorySize,
                         SMEM_BYTES);
    dim3 grid(256 / TX, 256 / TY, B);
    ssconv_main<<<grid, NTHREADS, SMEM_BYTES>>>(x, gi, bias, out, out + n_sel,
                                                write_idx);
}

// round 17
// speedup vs baseline: 1.0147x; 1.0147x over previous
#include <cuda_runtime.h>

// SSConv2d: per-pixel input-group routed 3x3 conv (64 oc) + maxout group select.
// fp32 FFMA2 path. Block = 32x8 output tile, 256 threads, 2 CTAs/SM (16 warps,
// RF-capped). 16 half-warp slots allocated to groups proportionally to work.
// Each slot holds its (tap,g) weight slice (16c x 4oc) in registers; the NEXT
// tap's slice is LDG'd into the same (dead) registers BEFORE the per-tap
// barrier. Interior entries are uint2 with precomputed byte offsets; edge
// pixels expand into dense per-(g,tap) buckets via a COMPACT EDGE-RECORD array
// built in pass A (pass C touches only edge pixels, no gidx reload/recompute).
// acc in padded smem tile with per-tap exclusive ownership (barrier between
// taps => race free, deterministic tap-order accumulation).

#define TX 32
#define TY 8
#define NPIX (TX * TY)      // 256
#define IN_W 34
#define IN_H 10
#define NIN (IN_W * IN_H)   // 340
#define ACC_STRIDE 68       // 68 floats = 272 B per pixel row
#define NTHREADS 256
#define FULL_CAP 184        // interior pixels: max 6*30 = 180
#define EDGE_CAP 164        // edge pixels: max 340-180 = 160
#define EPOOL_CAP 968       // edge expansion: max 160 px * 6 valid taps = 960

typedef unsigned long long ull;

// pre-packed weights: [tap(9)][g(4)][c2(8)][q(2)][ocg(16)][4 floats]
__device__ float g_wp[9 * 4 * 8 * 2 * 16 * 4];

__global__ void prepack_w(const float* __restrict__ w) {
    int i = blockIdx.x * blockDim.x + threadIdx.x;
    if (i >= 36864) return;
    int j   = i & 3;
    int ocg = (i >> 2) & 15;
    int q   = (i >> 6) & 1;
    int c2  = (i >> 7) & 7;
    int g   = (i >> 10) & 3;
    int tap = i >> 12;
    int oc = ocg * 4 + q * 2 + (j >> 1);
    int c  = c2 * 2 + (j & 1);
    g_wp[i] = w[(oc * 64 + g * 16 + c) * 9 + tap];
}

__device__ __forceinline__ void unpack2(float& lo, float& hi, ull v) {
    asm("mov.b64 {%0, %1}, %2;" : "=f"(lo), "=f"(hi) : "l"(v));
}
__device__ __forceinline__ ull pack2(float lo, float hi) {
    ull r;
    asm("mov.b64 %0, {%1, %2};" : "=l"(r) : "f"(lo), "f"(hi));
    return r;
}
__device__ __forceinline__ ull fma2(ull a, ull b, ull c) {
    ull d;
    asm("fma.rn.f32x2 %0, %1, %2, %3;" : "=l"(d) : "l"(a), "l"(b), "l"(c));
    return d;
}
__device__ __forceinline__ ull mul2(ull a, ull b) {
    ull d;
    asm("mul.rn.f32x2 %0, %1, %2;" : "=l"(d) : "l"(a), "l"(b));
    return d;
}
__device__ __forceinline__ ull add2(ull a, ull b) {
    ull d;
    asm("add.rn.f32x2 %0, %1, %2;" : "=l"(d) : "l"(a), "l"(b));
    return d;
}

struct PixAcc {
    ull a0, a1, a2, a3;
    float* ap;
};

// partial dot (16c x 4oc) for one pixel, byte-offset addressed
__device__ __forceinline__ PixAcc pix_compute(
    int xoffB, int accoffB, const char* xb, char* accb,
    const ull (&wA)[8], const ull (&wB)[8], const ull (&wC)[8], const ull (&wD)[8])
{
    PixAcc r;
    r.ap = (float*)(accb + accoffB);
    const ulonglong2* xp = (const ulonglong2*)(xb + xoffB);
    ulonglong2 p0 = xp[0];
    ulonglong2 p1 = xp[1];
    r.a0 = mul2(wA[0], p0.x);
    r.a1 = mul2(wB[0], p0.x);
    r.a2 = mul2(wC[0], p0.x);
    r.a3 = mul2(wD[0], p0.x);
    r.a0 = fma2(wA[1], p0.y, r.a0);
    r.a1 = fma2(wB[1], p0.y, r.a1);
    r.a2 = fma2(wC[1], p0.y, r.a2);
    r.a3 = fma2(wD[1], p0.y, r.a3);
    r.a0 = fma2(wA[2], p1.x, r.a0);
    r.a1 = fma2(wB[2], p1.x, r.a1);
    r.a2 = fma2(wC[2], p1.x, r.a2);
    r.a3 = fma2(wD[2], p1.x, r.a3);
    r.a0 = fma2(wA[3], p1.y, r.a0);
    r.a1 = fma2(wB[3], p1.y, r.a1);
    r.a2 = fma2(wC[3], p1.y, r.a2);
    r.a3 = fma2(wD[3], p1.y, r.a3);
    ulonglong2 p2 = xp[2];
    ulonglong2 p3 = xp[3];
    r.a0 = fma2(wA[4], p2.x, r.a0);
    r.a1 = fma2(wB[4], p2.x, r.a1);
    r.a2 = fma2(wC[4], p2.x, r.a2);
    r.a3 = fma2(wD[4], p2.x, r.a3);
    r.a0 = fma2(wA[5], p2.y, r.a0);
    r.a1 = fma2(wB[5], p2.y, r.a1);
    r.a2 = fma2(wC[5], p2.y, r.a2);
    r.a3 = fma2(wD[5], p2.y, r.a3);
    r.a0 = fma2(wA[6], p3.x, r.a0);
    r.a1 = fma2(wB[6], p3.x, r.a1);
    r.a2 = fma2(wC[6], p3.x, r.a2);
    r.a3 = fma2(wD[6], p3.x, r.a3);
    r.a0 = fma2(wA[7], p3.y, r.a0);
    r.a1 = fma2(wB[7], p3.y, r.a1);
    r.a2 = fma2(wC[7], p3.y, r.a2);
    r.a3 = fma2(wD[7], p3.y, r.a3);
    return r;
}

// commit (R12/R14 style): same-chain unpack/pack are register no-ops;
// 4 FADD + 2 packed adds into the acc row
__device__ __forceinline__ void pix_commit(const PixAcc& r) {
    ulonglong2* ap2 = (ulonglong2*)r.ap;
    ulonglong2 av = *ap2;
    float l, h, s0, s1, s2, s3;
    unpack2(l, h, r.a0); s0 = l + h;
    unpack2(l, h, r.a1); s1 = l + h;
    unpack2(l, h, r.a2); s2 = l + h;
    unpack2(l, h, r.a3); s3 = l + h;
    av.x = add2(av.x, pack2(s0, s1));
    av.y = add2(av.y, pack2(s2, s3));
    *ap2 = av;
}

#define SMEM_BYTES ((NIN * 16 + NPIX * ACC_STRIDE) * 4 + \
                    4 * FULL_CAP * 8 + EPOOL_CAP * 8 + EDGE_CAP * 8 + 464)

extern __shared__ float smem_dyn[];

__global__ __launch_bounds__(NTHREADS, 2)
void ssconv_main(const float* __restrict__ x, const int* __restrict__ gidx,
                 const float* __restrict__ bias, float* __restrict__ out,
                 float* __restrict__ out_idx, int write_idx) {
    float* x_s = smem_dyn;
    float* acc_s = x_s + NIN * 16;
    uint2* fl = (uint2*)(acc_s + NPIX * ACC_STRIDE);
    uint2* epool = fl + 4 * FULL_CAP;
    uint2* eraw = epool + EPOOL_CAP;         // compact edge records
    int* cntf = (int*)(eraw + EDGE_CAP);     // [4]
    int* cnte = cntf + 4;                    // [36] per-(g,tap) counts
    int* start_s = cnte + 36;                // [36] bucket starts
    int* cursor_s = start_s + 36;            // [36] fill cursors
    int* cnt_eraw = cursor_s + 36;           // [1]

    const int t = threadIdx.x;
    const int b = blockIdx.z;
    const int oy0 = blockIdx.y * TY;
    const int ox0 = blockIdx.x * TX;

    if (t < 41) cntf[t] = 0;   // cntf[4] + cnte[36] + cnt_eraw via layout order
    if (t == 41) cnt_eraw[0] = 0;
    __syncthreads();

    // ---- load input tile (with halo) into smem ----
    for (int f = t; f < NIN * 4; f += NTHREADS) {
        int p = f >> 2, c4 = f & 3;
        int ly = p / IN_W, lx = p - ly * IN_W;
        int iy = oy0 - 1 + ly, ix = ox0 - 1 + lx;
        float4 v = make_float4(0.f, 0.f, 0.f, 0.f);
        if ((unsigned)iy < 256u && (unsigned)ix < 256u)
            v = *(const float4*)(x + (((size_t)b * 256 + iy) * 256 + ix) * 16 + c4 * 4);
        *(float4*)(x_s + p * 16 + c4 * 4) = v;
    }
    // ---- pass A: classify; interior push, edge record + per-(g,tap) count ----
    for (int p = t; p < NIN; p += NTHREADS) {
        int ly = p / IN_W, lx = p - ly * IN_W;
        int iy = oy0 - 1 + ly, ix = ox0 - 1 + lx;
        if ((unsigned)iy < 256u && (unsigned)ix < 256u) {
            int g = gidx[((size_t)b * 256 + iy) * 256 + ix];
            unsigned xoffB = (unsigned)p * 64u;
            unsigned posB = (unsigned)(ly * TX + lx) * (ACC_STRIDE * 4);
            bool full = (ly >= 2) & (ly <= TY - 1) & (lx >= 2) & (lx <= TX - 1);
            if (full) {
                fl[g * FULL_CAP + atomicAdd(&cntf[g], 1)] =
                    make_uint2(xoffB, posB);
            } else {
                unsigned C = (lx <= TX - 1 ? 1u : 0u) |
                             ((lx >= 1 && lx <= TX ? 1u : 0u) << 1) |
                             ((lx >= 2 ? 1u : 0u) << 2);
                unsigned mask =
                    (ly <= TY - 1 ? C : 0u) |
                    ((ly >= 1 && ly <= TY ? C : 0u) << 3) |
                    ((ly >= 2 ? C : 0u) << 6);
                // compact record: x=xoffB, y=(g<<27)|(posB<<9)|mask
                eraw[atomicAdd(cnt_eraw, 1)] =
                    make_uint2(xoffB, ((unsigned)g << 27) | (posB << 9) | mask);
                for (int tp = 0; tp < 9; tp++)
                    if ((mask >> tp) & 1u) atomicAdd(&cnte[g * 9 + tp], 1);
            }
        }
    }
    // ---- init accumulators to bias (overlaps with counting) ----
    for (int f = t; f < NPIX * 17; f += NTHREADS) {
        int c4 = f % 17;
        float4 v = make_float4(0.f, 0.f, 0.f, 0.f);
        if (c4 < 16) v = *(const float4*)(bias + c4 * 4);
        ((float4*)acc_s)[f] = v;
    }
    __syncthreads();

    // ---- scan: bucket starts + cursors (single thread, 36 elems) ----
    if (t == 0) {
        int acc = 0;
        for (int i = 0; i < 36; i++) {
            start_s[i] = acc;
            cursor_s[i] = acc;
            acc += cnte[i];
        }
    }
    __syncthreads();

    // ---- pass C: expand compact edge records into dense buckets ----
    {
        const int ner = cnt_eraw[0];
        for (int i = t; i < ner; i += NTHREADS) {
            uint2 rec = eraw[i];
            unsigned mask = rec.y & 0x1FFu;
            unsigned posB = (rec.y >> 9) & 0x3FFFFu;
            int g = (int)(rec.y >> 27);
            for (int tp = 0; tp < 9; tp++) {
                if ((mask >> tp) & 1u) {
                    unsigned tapoffB =
                        (unsigned)(((tp / 3) * TX + (tp % 3)) * (ACC_STRIDE * 4));
                    int idx = atomicAdd(&cursor_s[g * 9 + tp], 1);
                    epool[idx] = make_uint2(rec.x, posB - tapoffB);
                }
            }
        }
    }
    __syncthreads();

    // ---- proportional slot allocation: 16 half-warp slots over 4 groups ----
    const int nf0 = cntf[0], nf1 = cntf[1], nf2 = cntf[2], nf3 = cntf[3];
    int ge0 = 0, ge1 = 0, ge2 = 0, ge3 = 0;
    for (int i = 0; i < 9; i++) {
        ge0 += cnte[i];
        ge1 += cnte[9 + i];
        ge2 += cnte[18 + i];
        ge3 += cnte[27 + i];
    }
    const int w0 = 4 * nf0 + ge0, w1 = 4 * nf1 + ge1;
    const int w2 = 4 * nf2 + ge2, w3 = 4 * nf3 + ge3;
    const int W = w0 + w1 + w2 + w3;   // never 0
    int e0 = 12 * w0 / W, e1 = 12 * w1 / W, e2 = 12 * w2 / W, e3 = 12 * w3 / W;
    int rem = 12 - (e0 + e1 + e2 + e3);
    int f0 = 12 * w0 - e0 * W, f1 = 12 * w1 - e1 * W;
    int f2 = 12 * w2 - e2 * W, f3 = 12 * w3 - e3 * W;
    int r0 = (f1 > f0) + (f2 > f0) + (f3 > f0);
    int r1 = (f0 >= f1) + (f2 > f1) + (f3 > f1);
    int r2 = (f0 >= f2) + (f1 >= f2) + (f3 > f2);
    int r3 = (f0 >= f3) + (f1 >= f3) + (f2 >= f3);
    int s0 = 1 + e0 + (r0 < rem), s1 = 1 + e1 + (r1 < rem);
    int s2 = 1 + e2 + (r2 < rem), s3 = 1 + e3 + (r3 < rem);
    const int S1 = s0, S2 = s0 + s1, S3 = s0 + s1 + s2;

    const int k = t >> 4;  // slot id 0..15
    const int g = (k >= S1) + (k >= S2) + (k >= S3);
    const int rank = k - (g == 0 ? 0 : g == 1 ? S1 : g == 2 ? S2 : S3);
    const int sg = (g == 0 ? s0 : g == 1 ? s1 : g == 2 ? s2 : s3);
    const int nf = (g == 0 ? nf0 : g == 1 ? nf1 : g == 2 ? nf2 : nf3);
    const uint2* Lf = fl + g * FULL_CAP;

    const int ocg = t & 15;
    const char* xb = (const char*)x_s;
    char* accb = (char*)acc_s + ocg * 16;

    // ---- preload tap 0 weights ----
    ull wA[8], wB[8], wC[8], wD[8];
    {
        const ulonglong2* wq = (const ulonglong2*)(g_wp + g * 1024) + ocg;
#pragma unroll
        for (int c2 = 0; c2 < 8; c2++) {
            ulonglong2 q0 = wq[c2 * 32];
            ulonglong2 q1 = wq[c2 * 32 + 16];
            wA[c2] = q0.x; wB[c2] = q0.y;
            wC[c2] = q1.x; wD[c2] = q1.y;
        }
    }

#pragma unroll 1
    for (int tap = 0; tap < 9; tap++) {
        const int ky = tap / 3;
        const int kx = tap - ky * 3;
        const int tapoffB = (ky * TX + kx) * (ACC_STRIDE * 4);

        // full-interior list: checkless, 2 pixels via one LDS.128 entry pair
        {
            int i = rank * 2;                // 16B-aligned pair start
            const int step = sg * 2;
            for (; i + 1 < nf; i += step) {
                uint4 uu = *(const uint4*)(Lf + i);
                PixAcc A = pix_compute((int)uu.x, (int)uu.y - tapoffB,
                                       xb, accb, wA, wB, wC, wD);
                PixAcc B = pix_compute((int)uu.z, (int)uu.w - tapoffB,
                                       xb, accb, wA, wB, wC, wD);
                pix_commit(A);
                pix_commit(B);
            }
            if (i < nf) {
                uint2 u0 = Lf[i];
                PixAcc A = pix_compute((int)u0.x, (int)u0.y - tapoffB,
                                       xb, accb, wA, wB, wC, wD);
                pix_commit(A);
            }
        }
        // dense edge bucket for (g, tap): branchless, zero decode (1-wide:
        // buckets are small; pairing reduces cross-slot parallelism — R16)
        {
            const int gt = g * 9 + tap;
            const int base = start_s[gt];
            const int n = cnte[gt];
            for (int i = rank; i < n; i += sg) {
                uint2 e = epool[base + i];
                PixAcc A = pix_compute((int)e.x, (int)e.y,
                                       xb, accb, wA, wB, wC, wD);
                pix_commit(A);
            }
        }

        // ---- prefetch NEXT tap's weights (float-unit pointer arithmetic!)
        //      into the now-dead registers BEFORE the barrier
        if (tap < 8) {
            const ulonglong2* wq =
                (const ulonglong2*)(g_wp + ((tap + 1) * 4 + g) * 1024) + ocg;
#pragma unroll
            for (int c2 = 0; c2 < 8; c2++) {
                ulonglong2 q0 = wq[c2 * 32];
                ulonglong2 q1 = wq[c2 * 32 + 16];
                wA[c2] = q0.x; wB[c2] = q0.y;
                wC[c2] = q1.x; wD[c2] = q1.y;
            }
        }
        __syncthreads();  // acc ownership handoff between taps
    }

    // ---- epilogue: maxout group selection, one thread per pixel ----
    {
        const float* ar = acc_s + t * ACC_STRIDE;
        float best = -3.4e38f;
        int bi = 0;
#pragma unroll
        for (int og = 0; og < 4; og++) {
            float m = -3.4e38f;
#pragma unroll
            for (int kk = 0; kk < 16; kk += 4) {
                float4 v = *(const float4*)(ar + og * 16 + kk);
                m = fmaxf(m, fmaxf(fmaxf(v.x, v.y), fmaxf(v.z, v.w)));
            }
            if (m > best) { best = m; bi = og; }  // first-max tie-break
        }
        int pyl = t >> 5, pxl = t & 31;
        size_t opix = ((size_t)b * 256 + (oy0 + pyl)) * 256 + (ox0 + pxl);
        float4* op = (float4*)(out + opix * 16);
        const float4* sp = (const float4*)(ar + bi * 16);
        op[0] = sp[0];
        op[1] = sp[1];
        op[2] = sp[2];
        op[3] = sp[3];
        if (write_idx) out_idx[opix] = (float)bi;
    }
}

extern "C" void kernel_launch(void* const* d_in, const int* in_sizes, int n_in,
                              void* d_out, int out_size) {
    const float* x = (const float*)d_in[0];
    const int* gi = (const int*)d_in[1];
    const float* w = (const float*)d_in[2];
    const float* bias = (const float*)d_in[3];
    float* out = (float*)d_out;

    const int n_sel = in_sizes[0];  // B*H*W*16 (sel output size)
    const int n_pix = in_sizes[1];  // B*H*W
    const int B = n_pix / (256 * 256);
    const int write_idx = (out_size >= n_sel + n_pix) ? 1 : 0;

    prepack_w<<<(36864 + 255) / 256, 256>>>(w);

    cudaFuncSetAttribute(ssconv_main, cudaFuncAttributeMaxDynamicSharedMemorySize,
                         SMEM_BYTES);
    dim3 grid(256 / TX, 256 / TY, B);
    ssconv_main<<<grid, NTHREADS, SMEM_BYTES>>>(x, gi, bias, out, out + n_sel,
                                                write_idx);
}